// round 1
// baseline (speedup 1.0000x reference)
#include <cuda_runtime.h>
#include <math.h>

#define BB  4
#define TT  1024
#define CC  1024
#define NH  16
#define NKVH 4
#define HD  64
#define BT  (BB*TT)
#define FFN 4096
#define CAD 32
#define VECH 12

// ---------------- scratch (static device memory; no runtime allocation) ----
__device__ float g_xn  [BT*CC];
__device__ float g_q   [BT*CC];
__device__ float g_k   [BT*NKVH*HD];
__device__ float g_v   [BT*NKVH*HD];
__device__ float g_y   [BT*CC];
__device__ float g_attn[BT*CC];
__device__ float g_cag [BT*CAD];
__device__ float g_cag2[BT*CAD];
__device__ float g_ca  [BT*CC];
__device__ float g_x1  [BT*CC];
__device__ float g_xm  [BT*CC];
__device__ float g_h   [(size_t)BT*FFN];
__device__ float g_h2  [(size_t)BT*FFN];
__device__ float g_gate[BT*CC];
__device__ float g_mlp [BT*CC];
__device__ float g_vit32[BT*CAD];
__device__ float g_vita[BT];
__device__ float g_vitb[BT];

// ---------------- helpers ---------------------------------------------------
__device__ __forceinline__ float geluf(float x){ return 0.5f*x*(1.0f+erff(x*0.70710678118654752f)); }
__device__ __forceinline__ float sigmf(float x){ return 1.0f/(1.0f+expf(-x)); }

// ---------------- generic NT SGEMM: C[M,N] = A[M,K] * B[N,K]^T --------------
// M % 128 == 0, K % 16 == 0 (true for all call sites). N guarded.
// EPI: 0 none, 1 relu^2, 2 sigmoid, 3 gelu
template<int EPI>
__global__ void __launch_bounds__(256) gemm_nt(const float* __restrict__ A,
                                               const float* __restrict__ Bm,
                                               float* __restrict__ Cm,
                                               int M, int N, int K)
{
    __shared__ float As[16][132];
    __shared__ float Bs[16][132];
    const int tid = threadIdx.x;
    const int bm  = blockIdx.y * 128;
    const int bn  = blockIdx.x * 128;
    const int tr  = tid >> 4;        // 0..15
    const int tc  = tid & 15;        // 0..15

    float acc[8][8];
    #pragma unroll
    for (int i = 0; i < 8; i++)
        #pragma unroll
        for (int j = 0; j < 8; j++) acc[i][j] = 0.f;

    for (int k0 = 0; k0 < K; k0 += 16) {
        #pragma unroll
        for (int it = 0; it < 2; it++) {
            int idx = tid + it*256;              // 0..511
            int r   = idx >> 2;                  // 0..127
            int c4  = idx & 3;                   // 0..3
            float4 av = *(const float4*)&A[(size_t)(bm+r)*K + k0 + c4*4];
            As[c4*4+0][r]=av.x; As[c4*4+1][r]=av.y; As[c4*4+2][r]=av.z; As[c4*4+3][r]=av.w;
            float4 bv = make_float4(0.f,0.f,0.f,0.f);
            if (bn + r < N) bv = *(const float4*)&Bm[(size_t)(bn+r)*K + k0 + c4*4];
            Bs[c4*4+0][r]=bv.x; Bs[c4*4+1][r]=bv.y; Bs[c4*4+2][r]=bv.z; Bs[c4*4+3][r]=bv.w;
        }
        __syncthreads();
        #pragma unroll
        for (int kk = 0; kk < 16; kk++) {
            float a[8], b[8];
            #pragma unroll
            for (int i = 0; i < 8; i++) a[i] = As[kk][tr*8+i];
            #pragma unroll
            for (int j = 0; j < 8; j++) b[j] = Bs[kk][tc*8+j];
            #pragma unroll
            for (int i = 0; i < 8; i++)
                #pragma unroll
                for (int j = 0; j < 8; j++) acc[i][j] += a[i]*b[j];
        }
        __syncthreads();
    }

    #pragma unroll
    for (int i = 0; i < 8; i++) {
        int row = bm + tr*8 + i;
        #pragma unroll
        for (int j = 0; j < 8; j++) {
            int col = bn + tc*8 + j;
            if (col < N) {
                float v = acc[i][j];
                if (EPI == 1) { v = fmaxf(v, 0.f); v = v*v; }
                else if (EPI == 2) { v = sigmf(v); }
                else if (EPI == 3) { v = geluf(v); }
                Cm[(size_t)row*N + col] = v;
            }
        }
    }
}

// ---------------- rmsnorm (one block per row of 1024) ----------------------
__global__ void rmsnorm_k(const float* __restrict__ in, float* __restrict__ out)
{
    __shared__ float red[256];
    int row = blockIdx.x;
    const float* r = in + (size_t)row*CC;
    float s = 0.f;
    for (int i = threadIdx.x; i < CC; i += 256) { float v = r[i]; s += v*v; }
    red[threadIdx.x] = s; __syncthreads();
    for (int st = 128; st > 0; st >>= 1) {
        if (threadIdx.x < st) red[threadIdx.x] += red[threadIdx.x+st];
        __syncthreads();
    }
    float scale = rsqrtf(red[0]/(float)CC + 1e-6f);
    for (int i = threadIdx.x; i < CC; i += 256) out[(size_t)row*CC + i] = r[i]*scale;
}

// ---------------- ve gate: v += 3*sigmoid(xn[:,:12]@wg^T) * ve --------------
__global__ void gatve_k(const float* __restrict__ xn, const float* __restrict__ ve,
                        const float* __restrict__ wg, float* __restrict__ v)
{
    int bt = blockIdx.x;
    int tid = threadIdx.x;            // 256 = NKVH*HD
    int kv  = tid >> 6;
    float dot = 0.f;
    #pragma unroll
    for (int c = 0; c < VECH; c++) dot += xn[(size_t)bt*CC + c] * wg[kv*VECH + c];
    float gate = 3.0f * sigmf(dot);
    size_t idx = (size_t)bt*256 + tid;
    v[idx] += gate * ve[idx];
}

// ---------------- rope + per-head rmsnorm * 1.2 (one warp per head) --------
__global__ void ropenorm_k(float* __restrict__ q, const float* __restrict__ cs,
                           const float* __restrict__ sn, int nheads)
{
    int gw   = (blockIdx.x * blockDim.x + threadIdx.x) >> 5;
    int lane = threadIdx.x & 31;
    int total = BT * nheads;
    if (gw >= total) return;
    int bt = gw / nheads, h = gw % nheads;
    int t  = bt % TT;
    float* p = q + ((size_t)bt*nheads + h)*HD;
    float x1 = p[lane], x2 = p[lane+32];
    float c = cs[t*32 + lane], s = sn[t*32 + lane];
    float o1 =  x1*c + x2*s;
    float o2 = -x1*s + x2*c;
    float ss = o1*o1 + o2*o2;
    #pragma unroll
    for (int m = 16; m > 0; m >>= 1) ss += __shfl_xor_sync(0xffffffffu, ss, m);
    float scale = rsqrtf(ss/64.f + 1e-6f) * 1.2f;
    p[lane]    = o1*scale;
    p[lane+32] = o2*scale;
}

// ---------------- flash attention with refine conv -------------------------
// Q:[BT,NH,64]  K,V:[BT,NKVH,64]  prev:[B,NH,T,T]  Y:[BT,NH,64]
__global__ void __launch_bounds__(256) flash_k(
    const float* __restrict__ Q, const float* __restrict__ K,
    const float* __restrict__ V, const float* __restrict__ prev,
    const float* __restrict__ rw, const float* __restrict__ alphap,
    float* __restrict__ Y)
{
    extern __shared__ float sm[];
    float* Qs = sm;                 // 64*65
    float* Ks = Qs + 64*65;
    float* Vs = Ks + 64*65;
    float* Ps = Vs + 64*65;
    float* Pv = Ps + 64*65;         // 66*68
    int tid = threadIdx.x;
    int tx = tid & 15, ty = tid >> 4;
    int qb = blockIdx.x;
    int bh = blockIdx.y;            // b*NH + h
    int b = bh >> 4, h = bh & 15;
    int kvh = h >> 2;
    int q0 = qb*64;
    float alpha = alphap[0];
    float w9[9];
    #pragma unroll
    for (int i = 0; i < 9; i++) w9[i] = rw[h*9 + i];

    for (int i = tid; i < 64*16; i += 256) {
        int r = i >> 4, c4 = i & 15;
        float4 v4 = *(const float4*)&Q[((size_t)(b*TT + q0 + r)*NH + h)*HD + c4*4];
        Qs[r*65+c4*4+0]=v4.x; Qs[r*65+c4*4+1]=v4.y; Qs[r*65+c4*4+2]=v4.z; Qs[r*65+c4*4+3]=v4.w;
    }

    float m[4], l[4], o[4][4];
    #pragma unroll
    for (int i = 0; i < 4; i++) {
        m[i] = -1e30f; l[i] = 0.f;
        #pragma unroll
        for (int j = 0; j < 4; j++) o[i][j] = 0.f;
    }
    const float* pbase = prev + (size_t)bh*TT*TT;

    for (int kc = 0; kc <= qb; kc++) {
        int k0 = kc*64;
        for (int i = tid; i < 64*16; i += 256) {
            int r = i >> 4, c4 = i & 15;
            size_t base = ((size_t)(b*TT + k0 + r)*NKVH + kvh)*HD + c4*4;
            float4 k4 = *(const float4*)&K[base];
            Ks[r*65+c4*4+0]=k4.x; Ks[r*65+c4*4+1]=k4.y; Ks[r*65+c4*4+2]=k4.z; Ks[r*65+c4*4+3]=k4.w;
            float4 v4 = *(const float4*)&V[base];
            Vs[r*65+c4*4+0]=v4.x; Vs[r*65+c4*4+1]=v4.y; Vs[r*65+c4*4+2]=v4.z; Vs[r*65+c4*4+3]=v4.w;
        }
        for (int i = tid; i < 66*66; i += 256) {
            int r = i/66, c = i - r*66;
            int gq = q0-1+r, gk = k0-1+c;
            float val = 0.f;
            if (gq >= 0 && gq < TT && gk >= 0 && gk < TT) val = pbase[(size_t)gq*TT + gk];
            Pv[r*68+c] = val;
        }
        __syncthreads();

        float s[4][4];
        #pragma unroll
        for (int i = 0; i < 4; i++)
            #pragma unroll
            for (int j = 0; j < 4; j++) s[i][j] = 0.f;
        #pragma unroll 8
        for (int d = 0; d < 64; d++) {
            float a[4], bb[4];
            #pragma unroll
            for (int i = 0; i < 4; i++) a[i]  = Qs[(ty*4+i)*65 + d];
            #pragma unroll
            for (int j = 0; j < 4; j++) bb[j] = Ks[(tx*4+j)*65 + d];
            #pragma unroll
            for (int i = 0; i < 4; i++)
                #pragma unroll
                for (int j = 0; j < 4; j++) s[i][j] += a[i]*bb[j];
        }
        #pragma unroll
        for (int i = 0; i < 4; i++) {
            int lr = ty*4+i;
            #pragma unroll
            for (int j = 0; j < 4; j++) {
                int lc = tx*4+j;
                float cv = 0.f;
                #pragma unroll
                for (int di = 0; di < 3; di++)
                    #pragma unroll
                    for (int dj = 0; dj < 3; dj++)
                        cv += Pv[(lr+di)*68 + lc+dj] * w9[di*3+dj];
                float val = s[i][j]*0.125f + alpha*cv;
                if (k0+lc > q0+lr) val = -1e30f;
                s[i][j] = val;
            }
        }
        // online softmax
        float mn[4], corr[4], rs[4];
        #pragma unroll
        for (int i = 0; i < 4; i++) {
            float rm = s[i][0];
            #pragma unroll
            for (int j = 1; j < 4; j++) rm = fmaxf(rm, s[i][j]);
            #pragma unroll
            for (int msk = 8; msk > 0; msk >>= 1)
                rm = fmaxf(rm, __shfl_xor_sync(0xffffffffu, rm, msk));
            mn[i] = fmaxf(m[i], rm);
            corr[i] = expf(m[i] - mn[i]);
        }
        #pragma unroll
        for (int i = 0; i < 4; i++) {
            float sum = 0.f;
            #pragma unroll
            for (int j = 0; j < 4; j++) { float p = expf(s[i][j] - mn[i]); s[i][j] = p; sum += p; }
            #pragma unroll
            for (int msk = 8; msk > 0; msk >>= 1)
                sum += __shfl_xor_sync(0xffffffffu, sum, msk);
            rs[i] = sum;
            l[i] = l[i]*corr[i] + rs[i];
            m[i] = mn[i];
            #pragma unroll
            for (int j = 0; j < 4; j++) o[i][j] *= corr[i];
        }
        #pragma unroll
        for (int i = 0; i < 4; i++)
            #pragma unroll
            for (int j = 0; j < 4; j++) Ps[(ty*4+i)*65 + tx*4+j] = s[i][j];
        __syncthreads();
        #pragma unroll 8
        for (int kk = 0; kk < 64; kk++) {
            float a[4], bb[4];
            #pragma unroll
            for (int i = 0; i < 4; i++) a[i]  = Ps[(ty*4+i)*65 + kk];
            #pragma unroll
            for (int j = 0; j < 4; j++) bb[j] = Vs[kk*65 + tx*4+j];
            #pragma unroll
            for (int i = 0; i < 4; i++)
                #pragma unroll
                for (int j = 0; j < 4; j++) o[i][j] += a[i]*bb[j];
        }
        __syncthreads();
    }

    #pragma unroll
    for (int i = 0; i < 4; i++) {
        float inv = 1.f/l[i];
        #pragma unroll
        for (int j = 0; j < 4; j++)
            Y[((size_t)(b*TT + q0 + ty*4 + i)*NH + h)*HD + tx*4 + j] = o[i][j]*inv;
    }
}

// ---------------- CA channel conv (+gelu): [B,T,32] ------------------------
__global__ void caconv_gelu_k(const float* __restrict__ g, const float* __restrict__ cw,
                              float* __restrict__ out)
{
    int idx = blockIdx.x*256 + threadIdx.x;          // over BT*CAD
    if (idx >= BT*CAD) return;
    int c = idx & 31;
    int bt = idx >> 5;
    int t = bt & (TT-1);
    float w0 = cw[c*3], w1 = cw[c*3+1], w2 = cw[c*3+2];
    float xm1 = (t > 0)     ? g[idx-CAD] : 0.f;
    float x0  = g[idx];
    float xp1 = (t < TT-1)  ? g[idx+CAD] : 0.f;
    float h = x0 + 0.1f*(w0*xm1 + w1*x0 + w2*xp1);
    out[idx] = geluf(h);
}

// ---------------- FFN depthwise conv step: out = in + 0.1*conv3_t ----------
__global__ void ffnconv_k(const float* __restrict__ in, const float* __restrict__ cw,
                          float* __restrict__ out)
{
    size_t idx = (size_t)blockIdx.x*256 + threadIdx.x;   // over BT*FFN
    int c = (int)(idx & (FFN-1));
    int bt = (int)(idx >> 12);
    int t = bt & (TT-1);
    float w0 = cw[c*3], w1 = cw[c*3+1], w2 = cw[c*3+2];
    float xm1 = (t > 0)    ? in[idx-FFN] : 0.f;
    float x0  = in[idx];
    float xp1 = (t < TT-1) ? in[idx+FFN] : 0.f;
    out[idx] = x0 + 0.1f*(w0*xm1 + w1*x0 + w2*xp1);
}

// ---------------- x1 = x + attn*(1 + 0.1*tanh(ca1)) ------------------------
__global__ void x1_k(const float* __restrict__ x, const float* __restrict__ attn,
                     const float* __restrict__ ca, float* __restrict__ x1)
{
    size_t i = (size_t)blockIdx.x*256 + threadIdx.x;
    x1[i] = x[i] + attn[i]*(1.0f + 0.1f*tanhf(ca[i]));
}

// ---------------- vit smoothing + threshold --------------------------------
__global__ void vitsm_k(const float* __restrict__ vin, float* __restrict__ vout)
{
    int idx = blockIdx.x*256 + threadIdx.x;   // BT
    if (idx >= BT) return;
    int b = idx >> 10, t = idx & (TT-1);
    const float* vb = vin + b*TT;
    float s = 0.f;
    #pragma unroll
    for (int o = -2; o <= 2; o++) {
        int tt = t + o;
        if (tt >= 0 && tt < TT) s += vb[tt];
    }
    s *= 0.2f;
    float v = 0.7f*vin[idx] + 0.3f*s;
    vout[idx] = (v > 0.3f) ? v : v*0.1f;
}

// ---------------- final: out = x1 + mlp*gate*(1+0.1*tanh(ca2))*vit ---------
__global__ void final_k(const float* __restrict__ x1, const float* __restrict__ mlp,
                        const float* __restrict__ gate, const float* __restrict__ ca,
                        const float* __restrict__ vit, float* __restrict__ out)
{
    size_t i = (size_t)blockIdx.x*256 + threadIdx.x;
    int row = (int)(i >> 10);
    float m = mlp[i]*gate[i]*(1.0f + 0.1f*tanhf(ca[i]));
    out[i] = x1[i] + m*vit[row];
}

// ---------------- host orchestration ---------------------------------------
static void launch_gemm(const float* A, const float* B, float* C,
                        int M, int N, int K, int epi)
{
    dim3 g((N+127)/128, M/128), b(256);
    switch (epi) {
        case 0: gemm_nt<0><<<g,b>>>(A,B,C,M,N,K); break;
        case 1: gemm_nt<1><<<g,b>>>(A,B,C,M,N,K); break;
        case 2: gemm_nt<2><<<g,b>>>(A,B,C,M,N,K); break;
        default: gemm_nt<3><<<g,b>>>(A,B,C,M,N,K); break;
    }
}

extern "C" void kernel_launch(void* const* d_in, const int* in_sizes, int n_in,
                              void* d_out, int out_size)
{
    const float* x       = (const float*)d_in[0];
    const float* ve      = (const float*)d_in[1];
    const float* cosb    = (const float*)d_in[2];
    const float* sinb    = (const float*)d_in[3];
    const float* prev    = (const float*)d_in[4];
    const float* w_q     = (const float*)d_in[5];
    const float* w_k     = (const float*)d_in[6];
    const float* w_v     = (const float*)d_in[7];
    const float* w_o     = (const float*)d_in[8];
    const float* w_veg   = (const float*)d_in[9];
    const float* refw    = (const float*)d_in[10];
    const float* ralpha  = (const float*)d_in[11];
    const float* ca_pi   = (const float*)d_in[12];
    const float* ca_cw   = (const float*)d_in[13];
    const float* ca_po   = (const float*)d_in[14];
    const float* ffn_in  = (const float*)d_in[15];
    const float* ffn_cw  = (const float*)d_in[16];
    const float* ffn_out = (const float*)d_in[17];
    const float* ffn_gate= (const float*)d_in[18];
    const float* vit_w1  = (const float*)d_in[19];
    const float* vit_w2  = (const float*)d_in[20];
    float* out = (float*)d_out;

    float *xn,*q,*k,*v,*y,*attn,*cag,*cag2,*ca,*x1,*xm,*h,*h2,*gate,*mlp,*vit32,*vita,*vitb;
    cudaGetSymbolAddress((void**)&xn,   g_xn);
    cudaGetSymbolAddress((void**)&q,    g_q);
    cudaGetSymbolAddress((void**)&k,    g_k);
    cudaGetSymbolAddress((void**)&v,    g_v);
    cudaGetSymbolAddress((void**)&y,    g_y);
    cudaGetSymbolAddress((void**)&attn, g_attn);
    cudaGetSymbolAddress((void**)&cag,  g_cag);
    cudaGetSymbolAddress((void**)&cag2, g_cag2);
    cudaGetSymbolAddress((void**)&ca,   g_ca);
    cudaGetSymbolAddress((void**)&x1,   g_x1);
    cudaGetSymbolAddress((void**)&xm,   g_xm);
    cudaGetSymbolAddress((void**)&h,    g_h);
    cudaGetSymbolAddress((void**)&h2,   g_h2);
    cudaGetSymbolAddress((void**)&gate, g_gate);
    cudaGetSymbolAddress((void**)&mlp,  g_mlp);
    cudaGetSymbolAddress((void**)&vit32,g_vit32);
    cudaGetSymbolAddress((void**)&vita, g_vita);
    cudaGetSymbolAddress((void**)&vitb, g_vitb);

    // 1. xn = rmsnorm(x)
    rmsnorm_k<<<BT, 256>>>(x, xn);
    // 2-4. q,k,v projections
    launch_gemm(xn, w_q, q, BT, CC, CC, 0);
    launch_gemm(xn, w_k, k, BT, NKVH*HD, CC, 0);
    launch_gemm(xn, w_v, v, BT, NKVH*HD, CC, 0);
    // 5. ve gate
    gatve_k<<<BT, 256>>>(xn, ve, w_veg, v);
    // 6-7. rope + head rmsnorm * 1.2
    ropenorm_k<<<(BT*NH)/8, 256>>>(q, cosb, sinb, NH);
    ropenorm_k<<<(BT*NKVH)/8, 256>>>(k, cosb, sinb, NKVH);
    // 8. flash attention with refine conv
    {
        size_t smem = (4*64*65 + 66*68) * sizeof(float);
        cudaFuncSetAttribute(flash_k, cudaFuncAttributeMaxDynamicSharedMemorySize, (int)smem);
        dim3 g(TT/64, BB*NH);
        flash_k<<<g, 256, smem>>>(q, k, v, prev, refw, ralpha, y);
    }
    // 9. attn_out = y @ w_o^T
    launch_gemm(y, w_o, attn, BT, CC, CC, 0);
    // 10-12. ca1 channel (on x)
    launch_gemm(x, ca_pi, cag, BT, CAD, CC, 0);
    caconv_gelu_k<<<(BT*CAD)/256, 256>>>(cag, ca_cw, cag2);
    launch_gemm(cag2, ca_po, ca, BT, CC, CAD, 0);
    // 13. x1
    x1_k<<<(BT*CC)/256, 256>>>(x, attn, ca, x1);
    // 14. xm = rmsnorm(x1)
    rmsnorm_k<<<BT, 256>>>(x1, xm);
    // 15. h = relu(xm@ffn_in^T)^2
    launch_gemm(xm, ffn_in, h, BT, FFN, CC, 1);
    // 16. 4 depthwise conv steps (ping-pong, ends in h)
    {
        int blocks = (int)(((size_t)BT*FFN)/256);
        ffnconv_k<<<blocks, 256>>>(h,  ffn_cw, h2);
        ffnconv_k<<<blocks, 256>>>(h2, ffn_cw, h);
        ffnconv_k<<<blocks, 256>>>(h,  ffn_cw, h2);
        ffnconv_k<<<blocks, 256>>>(h2, ffn_cw, h);
    }
    // 17. gate = sigmoid(xm@ffn_gate^T)
    launch_gemm(xm, ffn_gate, gate, BT, CC, CC, 2);
    // 18. mlp = h @ ffn_out^T
    launch_gemm(h, ffn_out, mlp, BT, CC, FFN, 0);
    // 19-21. ca2 channel (on x1)
    launch_gemm(x1, ca_pi, cag, BT, CAD, CC, 0);
    caconv_gelu_k<<<(BT*CAD)/256, 256>>>(cag, ca_cw, cag2);
    launch_gemm(cag2, ca_po, ca, BT, CC, CAD, 0);
    // 22-24. vit path
    launch_gemm(x1, vit_w1, vit32, BT, CAD, CC, 3);
    launch_gemm(vit32, vit_w2, vita, BT, 1, CAD, 2);
    vitsm_k<<<(BT+255)/256, 256>>>(vita, vitb);
    // 25. final
    final_k<<<(BT*CC)/256, 256>>>(x1, mlp, gate, ca, vitb, out);
}

// round 2
// speedup vs baseline: 1.3391x; 1.3391x over previous
#include <cuda_runtime.h>
#include <math.h>
#include <stdint.h>

#define BB  4
#define TT  1024
#define CC  1024
#define NH  16
#define NKVH 4
#define HD  64
#define BT  (BB*TT)
#define FFN 4096
#define CAD 32
#define VECH 12

// ---------------- scratch (static device memory; no runtime allocation) ----
__device__ float g_xn  [BT*CC];
__device__ float g_q   [BT*CC];
__device__ float g_k   [BT*NKVH*HD];
__device__ float g_v   [BT*NKVH*HD];
__device__ float g_y   [BT*CC];
__device__ float g_attn[BT*CC];
__device__ float g_cag [BT*CAD];
__device__ float g_cag2[BT*CAD];
__device__ float g_ca  [BT*CC];
__device__ float g_x1  [BT*CC];
__device__ float g_xm  [BT*CC];
__device__ float g_h   [(size_t)BT*FFN];
__device__ float g_h2  [(size_t)BT*FFN];
__device__ float g_gate[BT*CC];
__device__ float g_mlp [BT*CC];
__device__ float g_vit32[BT*CAD];
__device__ float g_vita[BT];
__device__ float g_vitb[BT];

// ---------------- helpers ---------------------------------------------------
__device__ __forceinline__ float geluf(float x){ return 0.5f*x*(1.0f+erff(x*0.70710678118654752f)); }
__device__ __forceinline__ float sigmf(float x){ return 1.0f/(1.0f+expf(-x)); }

__device__ __forceinline__ void split_tf32(float x, float& hi, float& lo){
    uint32_t h;
    asm("cvt.rna.tf32.f32 %0, %1;" : "=r"(h) : "f"(x));
    hi = __uint_as_float(h);
    float r = x - hi;
    uint32_t l;
    asm("cvt.rna.tf32.f32 %0, %1;" : "=r"(l) : "f"(r));
    lo = __uint_as_float(l);
}

__device__ __forceinline__ void mma_tf32(float* d, const float* a, const float* b){
    asm volatile("mma.sync.aligned.m16n8k8.row.col.f32.tf32.tf32.f32 "
        "{%0,%1,%2,%3}, {%4,%5,%6,%7}, {%8,%9}, {%0,%1,%2,%3};"
        : "+f"(d[0]), "+f"(d[1]), "+f"(d[2]), "+f"(d[3])
        : "r"(__float_as_uint(a[0])), "r"(__float_as_uint(a[1])),
          "r"(__float_as_uint(a[2])), "r"(__float_as_uint(a[3])),
          "r"(__float_as_uint(b[0])), "r"(__float_as_uint(b[1])));
}

// ---------------- 3xTF32 tensor-core NT GEMM --------------------------------
// C[M,N] = A[M,K] * B[N,K]^T.   M%128==0, K%32==0. N arbitrary (guarded).
// BM=128 BN=64 BK=32, 256 threads (8 warps as 4m x 2n), warp tile 32x32.
// smem: pre-split hi/lo tiles, row stride 36 floats (bank-conflict-free).
// EPI: 0 none, 1 relu^2, 2 sigmoid, 3 gelu
#define GSTRIDE 36
#define SM_A (128*GSTRIDE)
#define SM_B (64*GSTRIDE)
#define GEMM_SMEM ((2*SM_A + 2*SM_B)*4)

template<int EPI>
__global__ void __launch_bounds__(256, 2) gemm_tf32(const float* __restrict__ A,
                                                    const float* __restrict__ Bm,
                                                    float* __restrict__ Cm,
                                                    int M, int N, int K)
{
    extern __shared__ float sm[];
    float* Ah = sm;
    float* Al = Ah + SM_A;
    float* Bh = Al + SM_A;
    float* Bl = Bh + SM_B;

    const int tid  = threadIdx.x;
    const int bm   = blockIdx.y * 128;
    const int bn   = blockIdx.x * 64;
    const int wid  = tid >> 5, lane = tid & 31;
    const int wm   = wid & 3, wn = wid >> 2;      // 4m x 2n warps
    const int r    = lane >> 2;                    // 0..7
    const int kq   = lane & 3;                     // 0..3

    float acc[2][4][4];
    #pragma unroll
    for (int i = 0; i < 2; i++)
        #pragma unroll
        for (int j = 0; j < 4; j++)
            #pragma unroll
            for (int c = 0; c < 4; c++) acc[i][j][c] = 0.f;

    for (int k0 = 0; k0 < K; k0 += 32) {
        // ---- load + split A (128x32): 4 float4 per thread ----
        #pragma unroll
        for (int it = 0; it < 4; it++) {
            int g  = tid + it*256;          // 0..1023
            int m  = g >> 3;
            int kg = (g & 7) * 4;
            float4 v = *(const float4*)&A[(size_t)(bm+m)*K + k0 + kg];
            float4 h4, l4;
            split_tf32(v.x, h4.x, l4.x);
            split_tf32(v.y, h4.y, l4.y);
            split_tf32(v.z, h4.z, l4.z);
            split_tf32(v.w, h4.w, l4.w);
            *(float4*)&Ah[m*GSTRIDE + kg] = h4;
            *(float4*)&Al[m*GSTRIDE + kg] = l4;
        }
        // ---- load + split B (64x32): 2 float4 per thread ----
        #pragma unroll
        for (int it = 0; it < 2; it++) {
            int g  = tid + it*256;          // 0..511
            int n  = g >> 3;
            int kg = (g & 7) * 4;
            float4 v = make_float4(0.f,0.f,0.f,0.f);
            if (bn + n < N) v = *(const float4*)&Bm[(size_t)(bn+n)*K + k0 + kg];
            float4 h4, l4;
            split_tf32(v.x, h4.x, l4.x);
            split_tf32(v.y, h4.y, l4.y);
            split_tf32(v.z, h4.z, l4.z);
            split_tf32(v.w, h4.w, l4.w);
            *(float4*)&Bh[n*GSTRIDE + kg] = h4;
            *(float4*)&Bl[n*GSTRIDE + kg] = l4;
        }
        __syncthreads();

        #pragma unroll
        for (int ch = 0; ch < 4; ch++) {
            const int kb = ch*8 + kq;
            float ah[2][4], al[2][4];
            #pragma unroll
            for (int mt = 0; mt < 2; mt++) {
                int row = wm*32 + mt*16 + r;
                ah[mt][0] = Ah[row*GSTRIDE + kb];
                ah[mt][1] = Ah[(row+8)*GSTRIDE + kb];
                ah[mt][2] = Ah[row*GSTRIDE + kb + 4];
                ah[mt][3] = Ah[(row+8)*GSTRIDE + kb + 4];
                al[mt][0] = Al[row*GSTRIDE + kb];
                al[mt][1] = Al[(row+8)*GSTRIDE + kb];
                al[mt][2] = Al[row*GSTRIDE + kb + 4];
                al[mt][3] = Al[(row+8)*GSTRIDE + kb + 4];
            }
            float bh[4][2], bl[4][2];
            #pragma unroll
            for (int nt = 0; nt < 4; nt++) {
                int col = wn*32 + nt*8 + r;
                bh[nt][0] = Bh[col*GSTRIDE + kb];
                bh[nt][1] = Bh[col*GSTRIDE + kb + 4];
                bl[nt][0] = Bl[col*GSTRIDE + kb];
                bl[nt][1] = Bl[col*GSTRIDE + kb + 4];
            }
            #pragma unroll
            for (int mt = 0; mt < 2; mt++)
                #pragma unroll
                for (int nt = 0; nt < 4; nt++) {
                    mma_tf32(acc[mt][nt], ah[mt], bh[nt]);
                    mma_tf32(acc[mt][nt], ah[mt], bl[nt]);
                    mma_tf32(acc[mt][nt], al[mt], bh[nt]);
                }
        }
        __syncthreads();
    }

    // ---- epilogue ----
    #pragma unroll
    for (int mt = 0; mt < 2; mt++) {
        int row0 = bm + wm*32 + mt*16 + r;
        #pragma unroll
        for (int nt = 0; nt < 4; nt++) {
            int col0 = bn + wn*32 + nt*8 + kq*2;
            #pragma unroll
            for (int c = 0; c < 4; c++) {
                int row = row0 + (c >= 2 ? 8 : 0);
                int col = col0 + (c & 1);
                if (col < N) {
                    float v = acc[mt][nt][c];
                    if (EPI == 1) { v = fmaxf(v, 0.f); v = v*v; }
                    else if (EPI == 2) { v = sigmf(v); }
                    else if (EPI == 3) { v = geluf(v); }
                    Cm[(size_t)row*N + col] = v;
                }
            }
        }
    }
}

// ---------------- rmsnorm (one block per row of 1024) ----------------------
__global__ void rmsnorm_k(const float* __restrict__ in, float* __restrict__ out)
{
    __shared__ float red[256];
    int row = blockIdx.x;
    const float* r = in + (size_t)row*CC;
    float s = 0.f;
    for (int i = threadIdx.x; i < CC; i += 256) { float v = r[i]; s += v*v; }
    red[threadIdx.x] = s; __syncthreads();
    for (int st = 128; st > 0; st >>= 1) {
        if (threadIdx.x < st) red[threadIdx.x] += red[threadIdx.x+st];
        __syncthreads();
    }
    float scale = rsqrtf(red[0]/(float)CC + 1e-6f);
    for (int i = threadIdx.x; i < CC; i += 256) out[(size_t)row*CC + i] = r[i]*scale;
}

// ---------------- ve gate: v += 3*sigmoid(xn[:,:12]@wg^T) * ve --------------
__global__ void gatve_k(const float* __restrict__ xn, const float* __restrict__ ve,
                        const float* __restrict__ wg, float* __restrict__ v)
{
    int bt = blockIdx.x;
    int tid = threadIdx.x;            // 256 = NKVH*HD
    int kv  = tid >> 6;
    float dot = 0.f;
    #pragma unroll
    for (int c = 0; c < VECH; c++) dot += xn[(size_t)bt*CC + c] * wg[kv*VECH + c];
    float gate = 3.0f * sigmf(dot);
    size_t idx = (size_t)bt*256 + tid;
    v[idx] += gate * ve[idx];
}

// ---------------- rope + per-head rmsnorm * 1.2 (one warp per head) --------
__global__ void ropenorm_k(float* __restrict__ q, const float* __restrict__ cs,
                           const float* __restrict__ sn, int nheads)
{
    int gw   = (blockIdx.x * blockDim.x + threadIdx.x) >> 5;
    int lane = threadIdx.x & 31;
    int total = BT * nheads;
    if (gw >= total) return;
    int bt = gw / nheads, h = gw % nheads;
    int t  = bt % TT;
    float* p = q + ((size_t)bt*nheads + h)*HD;
    float x1 = p[lane], x2 = p[lane+32];
    float c = cs[t*32 + lane], s = sn[t*32 + lane];
    float o1 =  x1*c + x2*s;
    float o2 = -x1*s + x2*c;
    float ss = o1*o1 + o2*o2;
    #pragma unroll
    for (int m = 16; m > 0; m >>= 1) ss += __shfl_xor_sync(0xffffffffu, ss, m);
    float scale = rsqrtf(ss/64.f + 1e-6f) * 1.2f;
    p[lane]    = o1*scale;
    p[lane+32] = o2*scale;
}

// ---------------- flash attention with refine conv -------------------------
// Q:[BT,NH,64]  K,V:[BT,NKVH,64]  prev:[B,NH,T,T]  Y:[BT,NH,64]
__global__ void __launch_bounds__(256) flash_k(
    const float* __restrict__ Q, const float* __restrict__ K,
    const float* __restrict__ V, const float* __restrict__ prev,
    const float* __restrict__ rw, const float* __restrict__ alphap,
    float* __restrict__ Y)
{
    extern __shared__ float sm[];
    float* Qs = sm;                 // 64*65
    float* Ks = Qs + 64*65;
    float* Vs = Ks + 64*65;
    float* Ps = Vs + 64*65;
    float* Pv = Ps + 64*65;         // 66*68
    int tid = threadIdx.x;
    int tx = tid & 15, ty = tid >> 4;
    int qb = blockIdx.x;
    int bh = blockIdx.y;            // b*NH + h
    int b = bh >> 4, h = bh & 15;
    int kvh = h >> 2;
    int q0 = qb*64;
    float alpha = alphap[0];
    float w9[9];
    #pragma unroll
    for (int i = 0; i < 9; i++) w9[i] = rw[h*9 + i];

    for (int i = tid; i < 64*16; i += 256) {
        int r = i >> 4, c4 = i & 15;
        float4 v4 = *(const float4*)&Q[((size_t)(b*TT + q0 + r)*NH + h)*HD + c4*4];
        Qs[r*65+c4*4+0]=v4.x; Qs[r*65+c4*4+1]=v4.y; Qs[r*65+c4*4+2]=v4.z; Qs[r*65+c4*4+3]=v4.w;
    }

    float m[4], l[4], o[4][4];
    #pragma unroll
    for (int i = 0; i < 4; i++) {
        m[i] = -1e30f; l[i] = 0.f;
        #pragma unroll
        for (int j = 0; j < 4; j++) o[i][j] = 0.f;
    }
    const float* pbase = prev + (size_t)bh*TT*TT;

    for (int kc = 0; kc <= qb; kc++) {
        int k0 = kc*64;
        for (int i = tid; i < 64*16; i += 256) {
            int r = i >> 4, c4 = i & 15;
            size_t base = ((size_t)(b*TT + k0 + r)*NKVH + kvh)*HD + c4*4;
            float4 k4 = *(const float4*)&K[base];
            Ks[r*65+c4*4+0]=k4.x; Ks[r*65+c4*4+1]=k4.y; Ks[r*65+c4*4+2]=k4.z; Ks[r*65+c4*4+3]=k4.w;
            float4 v4 = *(const float4*)&V[base];
            Vs[r*65+c4*4+0]=v4.x; Vs[r*65+c4*4+1]=v4.y; Vs[r*65+c4*4+2]=v4.z; Vs[r*65+c4*4+3]=v4.w;
        }
        for (int i = tid; i < 66*66; i += 256) {
            int r = i/66, c = i - r*66;
            int gq = q0-1+r, gk = k0-1+c;
            float val = 0.f;
            if (gq >= 0 && gq < TT && gk >= 0 && gk < TT) val = pbase[(size_t)gq*TT + gk];
            Pv[r*68+c] = val;
        }
        __syncthreads();

        float s[4][4];
        #pragma unroll
        for (int i = 0; i < 4; i++)
            #pragma unroll
            for (int j = 0; j < 4; j++) s[i][j] = 0.f;
        #pragma unroll 8
        for (int d = 0; d < 64; d++) {
            float a[4], bb[4];
            #pragma unroll
            for (int i = 0; i < 4; i++) a[i]  = Qs[(ty*4+i)*65 + d];
            #pragma unroll
            for (int j = 0; j < 4; j++) bb[j] = Ks[(tx*4+j)*65 + d];
            #pragma unroll
            for (int i = 0; i < 4; i++)
                #pragma unroll
                for (int j = 0; j < 4; j++) s[i][j] += a[i]*bb[j];
        }
        #pragma unroll
        for (int i = 0; i < 4; i++) {
            int lr = ty*4+i;
            #pragma unroll
            for (int j = 0; j < 4; j++) {
                int lc = tx*4+j;
                float cv = 0.f;
                #pragma unroll
                for (int di = 0; di < 3; di++)
                    #pragma unroll
                    for (int dj = 0; dj < 3; dj++)
                        cv += Pv[(lr+di)*68 + lc+dj] * w9[di*3+dj];
                float val = s[i][j]*0.125f + alpha*cv;
                if (k0+lc > q0+lr) val = -1e30f;
                s[i][j] = val;
            }
        }
        // online softmax
        float mn[4], corr[4], rs[4];
        #pragma unroll
        for (int i = 0; i < 4; i++) {
            float rm = s[i][0];
            #pragma unroll
            for (int j = 1; j < 4; j++) rm = fmaxf(rm, s[i][j]);
            #pragma unroll
            for (int msk = 8; msk > 0; msk >>= 1)
                rm = fmaxf(rm, __shfl_xor_sync(0xffffffffu, rm, msk));
            mn[i] = fmaxf(m[i], rm);
            corr[i] = expf(m[i] - mn[i]);
        }
        #pragma unroll
        for (int i = 0; i < 4; i++) {
            float sum = 0.f;
            #pragma unroll
            for (int j = 0; j < 4; j++) { float p = expf(s[i][j] - mn[i]); s[i][j] = p; sum += p; }
            #pragma unroll
            for (int msk = 8; msk > 0; msk >>= 1)
                sum += __shfl_xor_sync(0xffffffffu, sum, msk);
            rs[i] = sum;
            l[i] = l[i]*corr[i] + rs[i];
            m[i] = mn[i];
            #pragma unroll
            for (int j = 0; j < 4; j++) o[i][j] *= corr[i];
        }
        #pragma unroll
        for (int i = 0; i < 4; i++)
            #pragma unroll
            for (int j = 0; j < 4; j++) Ps[(ty*4+i)*65 + tx*4+j] = s[i][j];
        __syncthreads();
        #pragma unroll 8
        for (int kk = 0; kk < 64; kk++) {
            float a[4], bb[4];
            #pragma unroll
            for (int i = 0; i < 4; i++) a[i]  = Ps[(ty*4+i)*65 + kk];
            #pragma unroll
            for (int j = 0; j < 4; j++) bb[j] = Vs[kk*65 + tx*4+j];
            #pragma unroll
            for (int i = 0; i < 4; i++)
                #pragma unroll
                for (int j = 0; j < 4; j++) o[i][j] += a[i]*bb[j];
        }
        __syncthreads();
    }

    #pragma unroll
    for (int i = 0; i < 4; i++) {
        float inv = 1.f/l[i];
        #pragma unroll
        for (int j = 0; j < 4; j++)
            Y[((size_t)(b*TT + q0 + ty*4 + i)*NH + h)*HD + tx*4 + j] = o[i][j]*inv;
    }
}

// ---------------- CA channel conv (+gelu): [B,T,32] ------------------------
__global__ void caconv_gelu_k(const float* __restrict__ g, const float* __restrict__ cw,
                              float* __restrict__ out)
{
    int idx = blockIdx.x*256 + threadIdx.x;          // over BT*CAD
    if (idx >= BT*CAD) return;
    int c = idx & 31;
    int bt = idx >> 5;
    int t = bt & (TT-1);
    float w0 = cw[c*3], w1 = cw[c*3+1], w2 = cw[c*3+2];
    float xm1 = (t > 0)     ? g[idx-CAD] : 0.f;
    float x0  = g[idx];
    float xp1 = (t < TT-1)  ? g[idx+CAD] : 0.f;
    float h = x0 + 0.1f*(w0*xm1 + w1*x0 + w2*xp1);
    out[idx] = geluf(h);
}

// ---------------- FFN depthwise conv step: out = in + 0.1*conv3_t ----------
__global__ void ffnconv_k(const float* __restrict__ in, const float* __restrict__ cw,
                          float* __restrict__ out)
{
    size_t idx = (size_t)blockIdx.x*256 + threadIdx.x;   // over BT*FFN
    int c = (int)(idx & (FFN-1));
    int bt = (int)(idx >> 12);
    int t = bt & (TT-1);
    float w0 = cw[c*3], w1 = cw[c*3+1], w2 = cw[c*3+2];
    float xm1 = (t > 0)    ? in[idx-FFN] : 0.f;
    float x0  = in[idx];
    float xp1 = (t < TT-1) ? in[idx+FFN] : 0.f;
    out[idx] = x0 + 0.1f*(w0*xm1 + w1*x0 + w2*xp1);
}

// ---------------- x1 = x + attn*(1 + 0.1*tanh(ca1)) ------------------------
__global__ void x1_k(const float* __restrict__ x, const float* __restrict__ attn,
                     const float* __restrict__ ca, float* __restrict__ x1)
{
    size_t i = (size_t)blockIdx.x*256 + threadIdx.x;
    x1[i] = x[i] + attn[i]*(1.0f + 0.1f*tanhf(ca[i]));
}

// ---------------- vit smoothing + threshold --------------------------------
__global__ void vitsm_k(const float* __restrict__ vin, float* __restrict__ vout)
{
    int idx = blockIdx.x*256 + threadIdx.x;   // BT
    if (idx >= BT) return;
    int b = idx >> 10, t = idx & (TT-1);
    const float* vb = vin + b*TT;
    float s = 0.f;
    #pragma unroll
    for (int o = -2; o <= 2; o++) {
        int tt = t + o;
        if (tt >= 0 && tt < TT) s += vb[tt];
    }
    s *= 0.2f;
    float v = 0.7f*vin[idx] + 0.3f*s;
    vout[idx] = (v > 0.3f) ? v : v*0.1f;
}

// ---------------- final: out = x1 + mlp*gate*(1+0.1*tanh(ca2))*vit ---------
__global__ void final_k(const float* __restrict__ x1, const float* __restrict__ mlp,
                        const float* __restrict__ gate, const float* __restrict__ ca,
                        const float* __restrict__ vit, float* __restrict__ out)
{
    size_t i = (size_t)blockIdx.x*256 + threadIdx.x;
    int row = (int)(i >> 10);
    float m = mlp[i]*gate[i]*(1.0f + 0.1f*tanhf(ca[i]));
    out[i] = x1[i] + m*vit[row];
}

// ---------------- host orchestration ---------------------------------------
static void launch_gemm(const float* A, const float* B, float* C,
                        int M, int N, int K, int epi)
{
    dim3 g((N+63)/64, M/128), b(256);
    static bool attr_set = false;
    if (!attr_set) {
        cudaFuncSetAttribute(gemm_tf32<0>, cudaFuncAttributeMaxDynamicSharedMemorySize, GEMM_SMEM);
        cudaFuncSetAttribute(gemm_tf32<1>, cudaFuncAttributeMaxDynamicSharedMemorySize, GEMM_SMEM);
        cudaFuncSetAttribute(gemm_tf32<2>, cudaFuncAttributeMaxDynamicSharedMemorySize, GEMM_SMEM);
        cudaFuncSetAttribute(gemm_tf32<3>, cudaFuncAttributeMaxDynamicSharedMemorySize, GEMM_SMEM);
        attr_set = true;
    }
    switch (epi) {
        case 0: gemm_tf32<0><<<g,b,GEMM_SMEM>>>(A,B,C,M,N,K); break;
        case 1: gemm_tf32<1><<<g,b,GEMM_SMEM>>>(A,B,C,M,N,K); break;
        case 2: gemm_tf32<2><<<g,b,GEMM_SMEM>>>(A,B,C,M,N,K); break;
        default: gemm_tf32<3><<<g,b,GEMM_SMEM>>>(A,B,C,M,N,K); break;
    }
}

extern "C" void kernel_launch(void* const* d_in, const int* in_sizes, int n_in,
                              void* d_out, int out_size)
{
    const float* x       = (const float*)d_in[0];
    const float* ve      = (const float*)d_in[1];
    const float* cosb    = (const float*)d_in[2];
    const float* sinb    = (const float*)d_in[3];
    const float* prev    = (const float*)d_in[4];
    const float* w_q     = (const float*)d_in[5];
    const float* w_k     = (const float*)d_in[6];
    const float* w_v     = (const float*)d_in[7];
    const float* w_o     = (const float*)d_in[8];
    const float* w_veg   = (const float*)d_in[9];
    const float* refw    = (const float*)d_in[10];
    const float* ralpha  = (const float*)d_in[11];
    const float* ca_pi   = (const float*)d_in[12];
    const float* ca_cw   = (const float*)d_in[13];
    const float* ca_po   = (const float*)d_in[14];
    const float* ffn_in  = (const float*)d_in[15];
    const float* ffn_cw  = (const float*)d_in[16];
    const float* ffn_out = (const float*)d_in[17];
    const float* ffn_gate= (const float*)d_in[18];
    const float* vit_w1  = (const float*)d_in[19];
    const float* vit_w2  = (const float*)d_in[20];
    float* out = (float*)d_out;

    float *xn,*q,*k,*v,*y,*attn,*cag,*cag2,*ca,*x1,*xm,*h,*h2,*gate,*mlp,*vit32,*vita,*vitb;
    cudaGetSymbolAddress((void**)&xn,   g_xn);
    cudaGetSymbolAddress((void**)&q,    g_q);
    cudaGetSymbolAddress((void**)&k,    g_k);
    cudaGetSymbolAddress((void**)&v,    g_v);
    cudaGetSymbolAddress((void**)&y,    g_y);
    cudaGetSymbolAddress((void**)&attn, g_attn);
    cudaGetSymbolAddress((void**)&cag,  g_cag);
    cudaGetSymbolAddress((void**)&cag2, g_cag2);
    cudaGetSymbolAddress((void**)&ca,   g_ca);
    cudaGetSymbolAddress((void**)&x1,   g_x1);
    cudaGetSymbolAddress((void**)&xm,   g_xm);
    cudaGetSymbolAddress((void**)&h,    g_h);
    cudaGetSymbolAddress((void**)&h2,   g_h2);
    cudaGetSymbolAddress((void**)&gate, g_gate);
    cudaGetSymbolAddress((void**)&mlp,  g_mlp);
    cudaGetSymbolAddress((void**)&vit32,g_vit32);
    cudaGetSymbolAddress((void**)&vita, g_vita);
    cudaGetSymbolAddress((void**)&vitb, g_vitb);

    // 1. xn = rmsnorm(x)
    rmsnorm_k<<<BT, 256>>>(x, xn);
    // 2-4. q,k,v projections
    launch_gemm(xn, w_q, q, BT, CC, CC, 0);
    launch_gemm(xn, w_k, k, BT, NKVH*HD, CC, 0);
    launch_gemm(xn, w_v, v, BT, NKVH*HD, CC, 0);
    // 5. ve gate
    gatve_k<<<BT, 256>>>(xn, ve, w_veg, v);
    // 6-7. rope + head rmsnorm * 1.2
    ropenorm_k<<<(BT*NH)/8, 256>>>(q, cosb, sinb, NH);
    ropenorm_k<<<(BT*NKVH)/8, 256>>>(k, cosb, sinb, NKVH);
    // 8. flash attention with refine conv
    {
        size_t smem = (4*64*65 + 66*68) * sizeof(float);
        cudaFuncSetAttribute(flash_k, cudaFuncAttributeMaxDynamicSharedMemorySize, (int)smem);
        dim3 g(TT/64, BB*NH);
        flash_k<<<g, 256, smem>>>(q, k, v, prev, refw, ralpha, y);
    }
    // 9. attn_out = y @ w_o^T
    launch_gemm(y, w_o, attn, BT, CC, CC, 0);
    // 10-12. ca1 channel (on x)
    launch_gemm(x, ca_pi, cag, BT, CAD, CC, 0);
    caconv_gelu_k<<<(BT*CAD)/256, 256>>>(cag, ca_cw, cag2);
    launch_gemm(cag2, ca_po, ca, BT, CC, CAD, 0);
    // 13. x1
    x1_k<<<(BT*CC)/256, 256>>>(x, attn, ca, x1);
    // 14. xm = rmsnorm(x1)
    rmsnorm_k<<<BT, 256>>>(x1, xm);
    // 15. h = relu(xm@ffn_in^T)^2
    launch_gemm(xm, ffn_in, h, BT, FFN, CC, 1);
    // 16. 4 depthwise conv steps (ping-pong, ends in h)
    {
        int blocks = (int)(((size_t)BT*FFN)/256);
        ffnconv_k<<<blocks, 256>>>(h,  ffn_cw, h2);
        ffnconv_k<<<blocks, 256>>>(h2, ffn_cw, h);
        ffnconv_k<<<blocks, 256>>>(h,  ffn_cw, h2);
        ffnconv_k<<<blocks, 256>>>(h2, ffn_cw, h);
    }
    // 17. gate = sigmoid(xm@ffn_gate^T)
    launch_gemm(xm, ffn_gate, gate, BT, CC, CC, 2);
    // 18. mlp = h @ ffn_out^T
    launch_gemm(h, ffn_out, mlp, BT, CC, FFN, 0);
    // 19-21. ca2 channel (on x1)
    launch_gemm(x1, ca_pi, cag, BT, CAD, CC, 0);
    caconv_gelu_k<<<(BT*CAD)/256, 256>>>(cag, ca_cw, cag2);
    launch_gemm(cag2, ca_po, ca, BT, CC, CAD, 0);
    // 22-24. vit path
    launch_gemm(x1, vit_w1, vit32, BT, CAD, CC, 3);
    launch_gemm(vit32, vit_w2, vita, BT, 1, CAD, 2);
    vitsm_k<<<(BT+255)/256, 256>>>(vita, vitb);
    // 25. final
    final_k<<<(BT*CC)/256, 256>>>(x1, mlp, gate, ca, vitb, out);
}